// round 2
// baseline (speedup 1.0000x reference)
#include <cuda_runtime.h>
#include <cstdint>
#include <cstddef>

// PoolingRetriever collapses: seqlen==1 -> softmax of a single logit == 1.0
// -> xi == ones through all 5 scan steps -> out = v = x@Wv.T + bv
// -> final = (x@Wv.T + bv) @ Wo.T + bo.   Wq/bq/Wk/bk/q_state are dead.

#define DIMX 768
#define NH   64
#define TM   64
#define LDSW 68   // padded row stride (floats): 68*4B=272B, 16B-aligned rows

// Pre-transposed weights (scratch; __device__ globals are allowed)
__device__ float g_WvT[DIMX * NH]; // [d][j]  = Wv[j][d]
__device__ float g_WoT[NH * DIMX]; // [j][i]  = Wo[i][j]

typedef unsigned long long u64t;

__device__ __forceinline__ u64t pack2(float lo, float hi) {
    u64t r; asm("mov.b64 %0, {%1, %2};" : "=l"(r) : "f"(lo), "f"(hi)); return r;
}
__device__ __forceinline__ void unpack2(u64t v, float& lo, float& hi) {
    asm("mov.b64 {%0, %1}, %2;" : "=f"(lo), "=f"(hi) : "l"(v));
}
// packed dual-FMA: d.lo += a.lo*b.lo ; d.hi += a.hi*b.hi  (FFMA2 in SASS)
__device__ __forceinline__ void fma2(u64t& d, u64t a, u64t b) {
    asm("fma.rn.f32x2 %0, %1, %2, %3;" : "=l"(d) : "l"(a), "l"(b), "l"(d));
}

__global__ void prep_kernel(const float* __restrict__ Wv,
                            const float* __restrict__ Wo) {
    int idx = blockIdx.x * blockDim.x + threadIdx.x;
    if (idx < DIMX * NH) {
        int d = idx / NH, j = idx % NH;
        g_WvT[idx] = Wv[j * DIMX + d];
    } else if (idx < 2 * DIMX * NH) {
        int t = idx - DIMX * NH;
        int j = t / DIMX, i = t % DIMX;
        g_WoT[t] = Wo[i * NH + j];
    }
}

__global__ __launch_bounds__(256) void fused_kernel(
        const float* __restrict__ x, const float* __restrict__ bv,
        const float* __restrict__ bo, float* __restrict__ out, int B) {
    // tmp_s[j][row]: stage-1 result, consumed K-major by stage 2
    __shared__ __align__(16) float tmp_s[NH][LDSW];
    // union buffer: stage1 {xs_t[32][68], ws_t[32][68]} / stage2 wo_s[64][68]
    __shared__ __align__(16) float buf[2 * 32 * LDSW];

    float (*xs)[LDSW] = (float(*)[LDSW])buf;               // [kk][row]
    float (*ws)[LDSW] = (float(*)[LDSW])(buf + 32 * LDSW); // [kk][j]
    float (*wo)[LDSW] = (float(*)[LDSW])buf;               // [k(j)][i]

    const int tid = threadIdx.x;
    const int tx = tid & 15;       // -> 4 output cols
    const int ty = tid >> 4;       // -> 4 output rows
    const int brow = blockIdx.x * TM;

    const int lc = tid & 31, lr = tid >> 5;  // x tile loader lanes
    const int wj = tid & 63, wk = tid >> 6;  // weight tile loader lanes

    // ---------------- Stage 1: tmp[64 rows][64 cols] = x @ Wv.T + bv --------
    u64t acc[4][2];
    {
        const int j0 = tx * 4;
        const float bv0 = bv[j0], bv1 = bv[j0 + 1];
        const float bv2 = bv[j0 + 2], bv3 = bv[j0 + 3];
        u64t p0 = pack2(bv0, bv1);
        u64t p1 = pack2(bv2, bv3);
        #pragma unroll
        for (int rr = 0; rr < 4; rr++) { acc[rr][0] = p0; acc[rr][1] = p1; }
    }

    for (int k0 = 0; k0 < DIMX; k0 += 32) {
        // xs_t[kk][row] <- x[brow+row][k0+kk]  (coalesced 128B per row)
        #pragma unroll
        for (int p = 0; p < 8; p++) {
            int r = lr + p * 8;
            int gr = brow + r; if (gr >= B) gr = B - 1;
            xs[lc][r] = x[(size_t)gr * DIMX + k0 + lc];
        }
        // ws_t[kk][j] <- WvT[k0+kk][j]  (coalesced, conflict-free store)
        #pragma unroll
        for (int p = 0; p < 8; p++) {
            int kk = wk + p * 4;
            ws[kk][wj] = g_WvT[(k0 + kk) * NH + wj];
        }
        __syncthreads();
        #pragma unroll
        for (int kk = 0; kk < 32; kk++) {
            float4 av = *(const float4*)&xs[kk][ty * 4];
            float4 bw = *(const float4*)&ws[kk][tx * 4];
            u64t b0 = pack2(bw.x, bw.y), b1 = pack2(bw.z, bw.w);
            u64t a0 = pack2(av.x, av.x), a1 = pack2(av.y, av.y);
            u64t a2 = pack2(av.z, av.z), a3 = pack2(av.w, av.w);
            fma2(acc[0][0], a0, b0); fma2(acc[0][1], a0, b1);
            fma2(acc[1][0], a1, b0); fma2(acc[1][1], a1, b1);
            fma2(acc[2][0], a2, b0); fma2(acc[2][1], a2, b1);
            fma2(acc[3][0], a3, b0); fma2(acc[3][1], a3, b1);
        }
        __syncthreads();
    }

    // tmp_s[j][row] = acc  (transposed store so stage 2 reads K-major)
    #pragma unroll
    for (int rr = 0; rr < 4; rr++) {
        float v0, v1, v2, v3;
        unpack2(acc[rr][0], v0, v1);
        unpack2(acc[rr][1], v2, v3);
        const int r = ty * 4 + rr, j0 = tx * 4;
        tmp_s[j0 + 0][r] = v0;
        tmp_s[j0 + 1][r] = v1;
        tmp_s[j0 + 2][r] = v2;
        tmp_s[j0 + 3][r] = v3;
    }
    __syncthreads();

    // ---------------- Stage 2: out[64 rows][768] = tmp @ Wo.T + bo ---------
    for (int i0 = 0; i0 < DIMX; i0 += 64) {
        // wo_s[j][i] <- WoT[j][i0+i]  (coalesced, conflict-free store)
        #pragma unroll
        for (int p = 0; p < 16; p++) {
            int j2 = wk + p * 4;
            wo[j2][wj] = g_WoT[j2 * DIMX + i0 + wj];
        }
        __syncthreads();

        u64t acc2[4][2];
        {
            const int i1 = i0 + tx * 4;
            u64t p0 = pack2(bo[i1], bo[i1 + 1]);
            u64t p1 = pack2(bo[i1 + 2], bo[i1 + 3]);
            #pragma unroll
            for (int rr = 0; rr < 4; rr++) { acc2[rr][0] = p0; acc2[rr][1] = p1; }
        }
        #pragma unroll
        for (int k = 0; k < NH; k++) {
            float4 av = *(const float4*)&tmp_s[k][ty * 4];
            float4 bw = *(const float4*)&wo[k][tx * 4];
            u64t b0 = pack2(bw.x, bw.y), b1 = pack2(bw.z, bw.w);
            u64t a0 = pack2(av.x, av.x), a1 = pack2(av.y, av.y);
            u64t a2 = pack2(av.z, av.z), a3 = pack2(av.w, av.w);
            fma2(acc2[0][0], a0, b0); fma2(acc2[0][1], a0, b1);
            fma2(acc2[1][0], a1, b0); fma2(acc2[1][1], a1, b1);
            fma2(acc2[2][0], a2, b0); fma2(acc2[2][1], a2, b1);
            fma2(acc2[3][0], a3, b0); fma2(acc2[3][1], a3, b1);
        }
        #pragma unroll
        for (int rr = 0; rr < 4; rr++) {
            int gr = brow + ty * 4 + rr;
            if (gr < B) {
                float4 o;
                unpack2(acc2[rr][0], o.x, o.y);
                unpack2(acc2[rr][1], o.z, o.w);
                *(float4*)&out[(size_t)gr * DIMX + i0 + tx * 4] = o;
            }
        }
        __syncthreads();
    }
}

extern "C" void kernel_launch(void* const* d_in, const int* in_sizes, int n_in,
                              void* d_out, int out_size) {
    // metadata order: x, q_state, Wq, bq, Wk, bk, Wv, bv, Wo, bo
    const float* x  = (const float*)d_in[0];
    const float* Wv = (const float*)d_in[6];
    const float* bv = (const float*)d_in[7];
    const float* Wo = (const float*)d_in[8];
    const float* bo = (const float*)d_in[9];
    float* out = (float*)d_out;

    const int B = in_sizes[0] / DIMX;

    prep_kernel<<<(2 * DIMX * NH + 255) / 256, 256>>>(Wv, Wo);
    const int grid = (B + TM - 1) / TM;
    fused_kernel<<<grid, 256>>>(x, bv, bo, out, B);
}